// round 10
// baseline (speedup 1.0000x reference)
#include <cuda_runtime.h>
#include <cuda_bf16.h>
#include <math.h>

#define NNODE 50000
#define DIM   128
#define NEDGE 400000
#define NHEAD 8

// ------------------------- device scratch -------------------------
__device__ float g_Ku[NNODE*DIM];
__device__ float g_Ki[NNODE*DIM];
__device__ float g_Qu[NNODE*DIM];
__device__ float g_Qi[NNODE*DIM];
__device__ float g_Vru[NNODE*DIM];
__device__ float g_Vri[NNODE*DIM];
__device__ float g_Vtu[NNODE*DIM];
__device__ float g_Vti[NNODE*DIM];
__device__ float g_ltu[NNODE*DIM];
__device__ float g_htu[NNODE*DIM];
__device__ float g_lti[NNODE*DIM];
__device__ float g_hti[NNODE*DIM];
__device__ float g_HZ0[NNODE*DIM];
__device__ float g_HZ1[NNODE*DIM];
__device__ float g_XP[NNODE*DIM];
__device__ float g_T[NNODE*DIM];
__device__ int   g_counts[2*NNODE];
__device__ int   g_cursor[2*NNODE];
__device__ int   g_offsets[2*NNODE+1];
__device__ int   g_bsums[128];
__device__ int   g_elist[2*NEDGE];
__device__ float g_fWku[DIM*DIM];
__device__ float g_fbku[DIM];
__device__ float g_fWki[DIM*DIM];
__device__ float g_fbki[DIM];
__device__ float g_fWvu[DIM*DIM];
__device__ float g_fbvu[DIM];
__device__ float g_fWvi[DIM*DIM];
__device__ float g_fbvi[DIM];

// ------------------------- zero an int buffer -------------------------
__global__ void zero_ints(int* __restrict__ p, int n) {
    int i = blockIdx.x * blockDim.x + threadIdx.x;
    if (i < n) p[i] = 0;
}

// --------------- fused weight build x4 (one launch, y selects) ---------------
__global__ void fuse_k4(const float* W0, const float* b0, const float* R0, float* fW0, float* fb0,
                        const float* W1, const float* b1, const float* R1, float* fW1, float* fb1,
                        const float* W2, const float* b2, const float* R2, float* fW2, float* fb2,
                        const float* W3, const float* b3, const float* R3, float* fW3, float* fb3) {
    int s = blockIdx.y;
    const float* Wk = s == 0 ? W0 : s == 1 ? W1 : s == 2 ? W2 : W3;
    const float* bk = s == 0 ? b0 : s == 1 ? b1 : s == 2 ? b2 : b3;
    const float* ra = s == 0 ? R0 : s == 1 ? R1 : s == 2 ? R2 : R3;
    float* fW = s == 0 ? fW0 : s == 1 ? fW1 : s == 2 ? fW2 : fW3;
    float* fb = s == 0 ? fb0 : s == 1 ? fb1 : s == 2 ? fb2 : fb3;
    int idx = blockIdx.x * blockDim.x + threadIdx.x;
    if (idx < DIM * DIM) {
        int j = idx >> 7, c = idx & 127;
        int h = c >> 4, k = c & 15;
        float sm = 0.f;
#pragma unroll
        for (int d = 0; d < 16; d++)
            sm += Wk[(j << 7) + (h << 4) + d] * ra[(h * 16 + d) * 16 + k];
        fW[idx] = sm;
    } else if (idx < DIM * DIM + DIM) {
        int c = idx - DIM * DIM;
        int h = c >> 4, k = c & 15;
        float sm = 0.f;
#pragma unroll
        for (int d = 0; d < 16; d++)
            sm += bk[(h << 4) + d] * ra[(h * 16 + d) * 16 + k];
        fb[c] = sm;
    }
}

// ===================== fp32 f32x2-FFMA GEMM, 4 problems in one launch =====================
__device__ __forceinline__ unsigned long long pk2(float lo, float hi) {
    unsigned long long r;
    asm("mov.b64 %0, {%1, %2};" : "=l"(r) : "f"(lo), "f"(hi));
    return r;
}
__device__ __forceinline__ void upk2(unsigned long long v, float &lo, float &hi) {
    asm("mov.b64 {%0, %1}, %2;" : "=f"(lo), "=f"(hi) : "l"(v));
}
__device__ __forceinline__ void ffma2(unsigned long long &d, unsigned long long a, unsigned long long b) {
    asm("fma.rn.f32x2 %0, %1, %2, %0;" : "+l"(d) : "l"(a), "l"(b));
}

__global__ __launch_bounds__(256) void gemm128_fp32_x4(
    const float* A0, const float* W0, const float* B0, float* C0,
    const float* A1, const float* W1, const float* B1, float* C1,
    const float* A2, const float* W2, const float* B2, float* C2,
    const float* A3, const float* W3, const float* B3, float* C3, int N)
{
    const int s = blockIdx.y;
    const float* A = s == 0 ? A0 : s == 1 ? A1 : s == 2 ? A2 : A3;
    const float* W = s == 0 ? W0 : s == 1 ? W1 : s == 2 ? W2 : W3;
    const float* bias = s == 0 ? B0 : s == 1 ? B1 : s == 2 ? B2 : B3;
    float* C = s == 0 ? C0 : s == 1 ? C1 : s == 2 ? C2 : C3;

    __shared__ __align__(16) float As[32][64];   // transposed: As[k][m]
    __shared__ __align__(16) float Ws[32][128];
    const int tid = threadIdx.x;
    const int tx = tid & 31, ty = tid >> 5;
    const int rowBase = blockIdx.x * 64;

    unsigned long long acc[8][2];
#pragma unroll
    for (int r = 0; r < 8; r++) { acc[r][0] = 0ull; acc[r][1] = 0ull; }

    for (int k0 = 0; k0 < DIM; k0 += 32) {
#pragma unroll
        for (int i = 0; i < 2; i++) {
            int row = (tid >> 3) + i * 32;
            int c4 = (tid & 7) * 4;
            int grow = rowBase + row;
            float4 v = make_float4(0.f, 0.f, 0.f, 0.f);
            if (grow < N) v = *(const float4*)(A + (size_t)grow * DIM + k0 + c4);
            As[c4 + 0][row] = v.x; As[c4 + 1][row] = v.y;
            As[c4 + 2][row] = v.z; As[c4 + 3][row] = v.w;
        }
#pragma unroll
        for (int i = 0; i < 4; i++) {
            int kr = (tid >> 5) + i * 8;
            *(float4*)&Ws[kr][(tid & 31) * 4] =
                *(const float4*)(W + (size_t)(k0 + kr) * DIM + (tid & 31) * 4);
        }
        __syncthreads();
#pragma unroll
        for (int k = 0; k < 32; k++) {
            float4 a0 = *(float4*)&As[k][ty * 8];
            float4 a1 = *(float4*)&As[k][ty * 8 + 4];
            float4 w  = *(float4*)&Ws[k][tx * 4];
            unsigned long long wp0 = pk2(w.x, w.y);
            unsigned long long wp1 = pk2(w.z, w.w);
            float ar[8] = {a0.x, a0.y, a0.z, a0.w, a1.x, a1.y, a1.z, a1.w};
#pragma unroll
            for (int r = 0; r < 8; r++) {
                unsigned long long ap = pk2(ar[r], ar[r]);
                ffma2(acc[r][0], ap, wp0);
                ffma2(acc[r][1], ap, wp1);
            }
        }
        __syncthreads();
    }

    const int col = tx * 4;
    float b0 = bias[col], b1 = bias[col + 1], b2 = bias[col + 2], b3 = bias[col + 3];
#pragma unroll
    for (int r = 0; r < 8; r++) {
        int grow = rowBase + ty * 8 + r;
        if (grow < N) {
            float o0, o1, o2, o3;
            upk2(acc[r][0], o0, o1); upk2(acc[r][1], o2, o3);
            *(float4*)(C + (size_t)grow * DIM + col) =
                make_float4(o0 + b0, o1 + b1, o2 + b2, o3 + b3);
        }
    }
}

// ===================== bf16x3 tensor-core GEMM (batched via blockIdx.y) =====================
// Runtime min-mode: 0 -> A ; 1 -> A+A2 ; 2 -> A-A2.
// ACT_: 0 none, 1 tanh.  MOUT_: 0 plain ; 1 -> sigmoid-skip blend with Dres.
#define BM 128
#define BK 32
#define APAD 40
#define BPAD 136

struct GemmJob {
    const float* A; const float* A2; const float* W; const float* bias;
    const float* Dres; const float* skipp; float* C; int minmode;
};

__device__ __forceinline__ void mma_bf16(float* c, const unsigned* a, const unsigned* b) {
    asm volatile(
        "mma.sync.aligned.m16n8k16.row.col.f32.bf16.bf16.f32 "
        "{%0,%1,%2,%3}, {%4,%5,%6,%7}, {%8,%9}, {%0,%1,%2,%3};"
        : "+f"(c[0]), "+f"(c[1]), "+f"(c[2]), "+f"(c[3])
        : "r"(a[0]), "r"(a[1]), "r"(a[2]), "r"(a[3]), "r"(b[0]), "r"(b[1]));
}

template<int ACT_, int MOUT_, int NJOBS>
__global__ __launch_bounds__(256) void gemm128_bf16_batch(GemmJob j0, GemmJob j1, GemmJob j2,
                                                          GemmJob j3, GemmJob j4, GemmJob j5, int N)
{
    GemmJob jb = j0;
    if (NJOBS > 1 && blockIdx.y == 1) jb = j1;
    if (NJOBS > 2 && blockIdx.y == 2) jb = j2;
    if (NJOBS > 3 && blockIdx.y == 3) jb = j3;
    if (NJOBS > 4 && blockIdx.y == 4) jb = j4;
    if (NJOBS > 5 && blockIdx.y == 5) jb = j5;
    const float* __restrict__ A = jb.A;
    const float* __restrict__ A2 = jb.A2;
    const float* __restrict__ W = jb.W;
    const float* __restrict__ bias = jb.bias;
    const int minmode = jb.minmode;

    __shared__ __align__(16) __nv_bfloat16 Ah[BM * APAD];
    __shared__ __align__(16) __nv_bfloat16 Al[BM * APAD];
    __shared__ __align__(16) __nv_bfloat16 Bh[BK * BPAD];
    __shared__ __align__(16) __nv_bfloat16 Bl[BK * BPAD];

    const int tid = threadIdx.x;
    const int lane = tid & 31;
    const int wid = tid >> 5;
    const int warp_m = (wid >> 2) * 64;
    const int warp_n = (wid & 3) * 32;
    const int rowBase = blockIdx.x * BM;

    float acc[4][4][4];
#pragma unroll
    for (int i = 0; i < 4; i++)
#pragma unroll
        for (int j = 0; j < 4; j++)
#pragma unroll
            for (int r = 0; r < 4; r++) acc[i][j][r] = 0.f;

    for (int k0 = 0; k0 < DIM; k0 += BK) {
#pragma unroll
        for (int it = 0; it < 4; it++) {
            int idx = tid + it * 256;
            int row = idx >> 3;
            int c4 = (idx & 7) * 4;
            int grow = rowBase + row;
            float4 v = make_float4(0.f, 0.f, 0.f, 0.f);
            if (grow < N) {
                v = *(const float4*)(A + (size_t)grow * DIM + k0 + c4);
                if (minmode == 1) {
                    float4 b = *(const float4*)(A2 + (size_t)grow * DIM + k0 + c4);
                    v.x += b.x; v.y += b.y; v.z += b.z; v.w += b.w;
                } else if (minmode == 2) {
                    float4 b = *(const float4*)(A2 + (size_t)grow * DIM + k0 + c4);
                    v.x -= b.x; v.y -= b.y; v.z -= b.z; v.w -= b.w;
                }
            }
            float f[4] = {v.x, v.y, v.z, v.w};
            __nv_bfloat16 h[4], l[4];
#pragma unroll
            for (int q = 0; q < 4; q++) {
                h[q] = __float2bfloat16(f[q]);
                l[q] = __float2bfloat16(f[q] - __bfloat162float(h[q]));
            }
            __nv_bfloat162 p;
            p.x = h[0]; p.y = h[1]; *(__nv_bfloat162*)&Ah[row * APAD + c4] = p;
            p.x = h[2]; p.y = h[3]; *(__nv_bfloat162*)&Ah[row * APAD + c4 + 2] = p;
            p.x = l[0]; p.y = l[1]; *(__nv_bfloat162*)&Al[row * APAD + c4] = p;
            p.x = l[2]; p.y = l[3]; *(__nv_bfloat162*)&Al[row * APAD + c4 + 2] = p;
        }
#pragma unroll
        for (int it = 0; it < 4; it++) {
            int idx = tid + it * 256;
            int kr = idx >> 5;
            int c4 = (idx & 31) * 4;
            float4 v = *(const float4*)(W + (size_t)(k0 + kr) * DIM + c4);
            float f[4] = {v.x, v.y, v.z, v.w};
            __nv_bfloat16 h[4], l[4];
#pragma unroll
            for (int q = 0; q < 4; q++) {
                h[q] = __float2bfloat16(f[q]);
                l[q] = __float2bfloat16(f[q] - __bfloat162float(h[q]));
            }
            __nv_bfloat162 p;
            p.x = h[0]; p.y = h[1]; *(__nv_bfloat162*)&Bh[kr * BPAD + c4] = p;
            p.x = h[2]; p.y = h[3]; *(__nv_bfloat162*)&Bh[kr * BPAD + c4 + 2] = p;
            p.x = l[0]; p.y = l[1]; *(__nv_bfloat162*)&Bl[kr * BPAD + c4] = p;
            p.x = l[2]; p.y = l[3]; *(__nv_bfloat162*)&Bl[kr * BPAD + c4 + 2] = p;
        }
        __syncthreads();

#pragma unroll
        for (int ks = 0; ks < BK; ks += 16) {
            unsigned bh[4][2], bl[4][2];
#pragma unroll
            for (int j = 0; j < 4; j++) {
                int r = ks + (lane & 15);
                int cc = warp_n + j * 8;
                unsigned ab = (unsigned)__cvta_generic_to_shared(&Bh[r * BPAD + cc]);
                asm volatile("ldmatrix.sync.aligned.m8n8.x2.trans.shared.b16 {%0,%1}, [%2];"
                             : "=r"(bh[j][0]), "=r"(bh[j][1]) : "r"(ab));
                unsigned abl = (unsigned)__cvta_generic_to_shared(&Bl[r * BPAD + cc]);
                asm volatile("ldmatrix.sync.aligned.m8n8.x2.trans.shared.b16 {%0,%1}, [%2];"
                             : "=r"(bl[j][0]), "=r"(bl[j][1]) : "r"(abl));
            }
#pragma unroll
            for (int i = 0; i < 4; i++) {
                int r = warp_m + i * 16 + (lane & 15);
                int cc = ks + (lane >> 4) * 8;
                unsigned ah[4], al[4];
                unsigned aa = (unsigned)__cvta_generic_to_shared(&Ah[r * APAD + cc]);
                asm volatile("ldmatrix.sync.aligned.m8n8.x4.shared.b16 {%0,%1,%2,%3}, [%4];"
                             : "=r"(ah[0]), "=r"(ah[1]), "=r"(ah[2]), "=r"(ah[3]) : "r"(aa));
                unsigned aal = (unsigned)__cvta_generic_to_shared(&Al[r * APAD + cc]);
                asm volatile("ldmatrix.sync.aligned.m8n8.x4.shared.b16 {%0,%1,%2,%3}, [%4];"
                             : "=r"(al[0]), "=r"(al[1]), "=r"(al[2]), "=r"(al[3]) : "r"(aal));
#pragma unroll
                for (int j = 0; j < 4; j++) {
                    mma_bf16(acc[i][j], ah, bh[j]);
                    mma_bf16(acc[i][j], ah, bl[j]);
                    mma_bf16(acc[i][j], al, bh[j]);
                }
            }
        }
        __syncthreads();
    }

    float alpha = 1.f, onem = 0.f;
    if (MOUT_ == 1) {
        float s = *jb.skipp;
        alpha = 1.f / (1.f + __expf(-s));
        onem = 1.f - alpha;
    }
    const int g = lane >> 2, t = lane & 3;
#pragma unroll
    for (int i = 0; i < 4; i++) {
        int r0 = rowBase + warp_m + i * 16 + g;
        int r1 = r0 + 8;
#pragma unroll
        for (int j = 0; j < 4; j++) {
            int col = warp_n + j * 8 + t * 2;
            float b0 = bias[col], b1 = bias[col + 1];
            float o0 = acc[i][j][0] + b0, o1 = acc[i][j][1] + b1;
            float o2 = acc[i][j][2] + b0, o3 = acc[i][j][3] + b1;
            if (ACT_ == 1) { o0 = tanhf(o0); o1 = tanhf(o1); o2 = tanhf(o2); o3 = tanhf(o3); }
            if (r0 < N) {
                if (MOUT_ == 1) {
                    float2 dr = *(const float2*)(jb.Dres + (size_t)r0 * DIM + col);
                    o0 = o0 * alpha + dr.x * onem;
                    o1 = o1 * alpha + dr.y * onem;
                }
                float2 ov; ov.x = o0; ov.y = o1;
                *(float2*)(jb.C + (size_t)r0 * DIM + col) = ov;
            }
            if (r1 < N) {
                if (MOUT_ == 1) {
                    float2 dr = *(const float2*)(jb.Dres + (size_t)r1 * DIM + col);
                    o2 = o2 * alpha + dr.x * onem;
                    o3 = o3 * alpha + dr.y * onem;
                }
                float2 ov; ov.x = o2; ov.y = o3;
                *(float2*)(jb.C + (size_t)r1 * DIM + col) = ov;
            }
        }
    }
}

// ------------------------- CSR build: BOTH relations in one pass -------------------------
__global__ void count_edges2(const int* __restrict__ bd, const int* __restrict__ rd,
                             int* __restrict__ counts) {
    int e = blockIdx.x * blockDim.x + threadIdx.x;
    if (e < NEDGE) atomicAdd(&counts[bd[e]], 1);
    else if (e < 2 * NEDGE) atomicAdd(&counts[NNODE + rd[e - NEDGE]], 1);
}

__global__ void scan_blocks(const int* __restrict__ counts, int* __restrict__ offsets,
                            int* __restrict__ bsums, int n) {
    __shared__ int sh[1024];
    int tid = threadIdx.x;
    int i = blockIdx.x * 1024 + tid;
    int v = (i < n) ? counts[i] : 0;
    sh[tid] = v;
    __syncthreads();
    for (int off = 1; off < 1024; off <<= 1) {
        int t = (tid >= off) ? sh[tid - off] : 0;
        __syncthreads();
        sh[tid] += t;
        __syncthreads();
    }
    if (i < n) offsets[i + 1] = sh[tid];
    if (tid == 1023) bsums[blockIdx.x] = sh[1023];
}

__global__ void scan_sums(int* __restrict__ bsums, int nb) {
    __shared__ int sh[128];
    int tid = threadIdx.x;
    int v = (tid < nb) ? bsums[tid] : 0;
    sh[tid] = v;
    __syncthreads();
    for (int off = 1; off < 128; off <<= 1) {
        int t = (tid >= off) ? sh[tid - off] : 0;
        __syncthreads();
        sh[tid] += t;
        __syncthreads();
    }
    if (tid < nb) bsums[tid] = sh[tid] - v;
}

__global__ void add_carry(int* __restrict__ offsets, const int* __restrict__ bsums,
                          int* __restrict__ cursor, int n) {
    int i = blockIdx.x * 1024 + threadIdx.x;
    if (i < n) {
        offsets[i + 1] += bsums[blockIdx.x];
        cursor[i] = 0;
    }
    if (i == 0) offsets[0] = 0;
}

__global__ void scatter_edges2(const int* __restrict__ bs, const int* __restrict__ bd,
                               const int* __restrict__ rs, const int* __restrict__ rd,
                               const int* __restrict__ offsets, int* __restrict__ cursor,
                               int* __restrict__ elist) {
    int e = blockIdx.x * blockDim.x + threadIdx.x;
    if (e < NEDGE) {
        int d = bd[e];
        int p = atomicAdd(&cursor[d], 1);
        elist[offsets[d] + p] = bs[e];
    } else if (e < 2 * NEDGE) {
        int d = NNODE + rd[e - NEDGE];
        int p = atomicAdd(&cursor[d], 1);
        elist[offsets[d] + p] = rs[e - NEDGE];
    }
}

// ---------------- fused attention: both relations, online softmax, one pass ----------------
__global__ void attn_agg2(const float* __restrict__ Qi, const float* __restrict__ Ku,
                          const float* __restrict__ Vtu,
                          const float* __restrict__ Qu, const float* __restrict__ Ki,
                          const float* __restrict__ Vti,
                          const int* __restrict__ offsets, const int* __restrict__ elist,
                          const float* __restrict__ pri,
                          float* __restrict__ lti, float* __restrict__ hti,
                          float* __restrict__ ltu, float* __restrict__ htu)
{
    int w = (blockIdx.x * blockDim.x + threadIdx.x) >> 5;
    int lane = threadIdx.x & 31;
    if (w >= 2 * NNODE) return;
    const bool rel0 = (w < NNODE);
    const int node = rel0 ? w : w - NNODE;
    const float* Q = rel0 ? Qi : Qu;
    const float* K = rel0 ? Ku : Ki;
    const float* V = rel0 ? Vtu : Vti;
    float* lt_out = rel0 ? lti : ltu;
    float* ht_out = rel0 ? hti : htu;
    const int beg = offsets[w], end = offsets[w + 1];
    const int h = lane >> 2;
    const float scale = pri[(rel0 ? 0 : NHEAD) + h] * 0.25f;
    float4 q = *(const float4*)(Q + (size_t)node * DIM + lane * 4);

    float m_lf = __int_as_float(0xff800000), m_hf = m_lf;
    float z_lf = 0.f, z_hf = 0.f;
    float4 alt = make_float4(0.f, 0.f, 0.f, 0.f);
    float4 aht = make_float4(0.f, 0.f, 0.f, 0.f);

    for (int e = beg; e < end; e++) {
        int s = elist[e];
        float4 kv = *(const float4*)(K + (size_t)s * DIM + lane * 4);
        float p = q.x * kv.x + q.y * kv.y + q.z * kv.z + q.w * kv.w;
        p += __shfl_xor_sync(0xffffffffu, p, 1);
        p += __shfl_xor_sync(0xffffffffu, p, 2);
        float raw = p * scale;
        float inv = 1.0f / (raw + 1e-6f);
        // online rescale (branch rarely taken after warmup)
        if (raw > m_lf) {
            float sc = __expf(m_lf - raw);
            z_lf *= sc; alt.x *= sc; alt.y *= sc; alt.z *= sc; alt.w *= sc;
            m_lf = raw;
        }
        if (inv > m_hf) {
            float sc = __expf(m_hf - inv);
            z_hf *= sc; aht.x *= sc; aht.y *= sc; aht.z *= sc; aht.w *= sc;
            m_hf = inv;
        }
        float elf = __expf(raw - m_lf);
        float ehf = __expf(inv - m_hf);
        z_lf += elf; z_hf += ehf;
        float4 v = *(const float4*)(V + (size_t)s * DIM + lane * 4);
        alt.x += v.x * elf; alt.y += v.y * elf; alt.z += v.z * elf; alt.w += v.w * elf;
        aht.x += v.x * ehf; aht.y += v.y * ehf; aht.z += v.z * ehf; aht.w += v.w * ehf;
    }
    float izl = (end > beg) ? 1.0f / z_lf : 0.f;
    float izh = (end > beg) ? 1.0f / z_hf : 0.f;
    *(float4*)(lt_out + (size_t)node * DIM + lane * 4) =
        make_float4(alt.x * izl, alt.y * izl, alt.z * izl, alt.w * izl);
    *(float4*)(ht_out + (size_t)node * DIM + lane * 4) =
        make_float4(aht.x * izh, aht.y * izh, aht.z * izh, aht.w * izh);
}

// ------------------------- gate scores + blended T (both node types) -------------------------
__global__ void compute_T2(const float* __restrict__ Vru, const float* __restrict__ ltu,
                           const float* __restrict__ htu, const float* __restrict__ HZ0u,
                           const float* __restrict__ HZ1u, const float* __restrict__ XPu,
                           float* __restrict__ Tu,
                           const float* __restrict__ Vri, const float* __restrict__ lti,
                           const float* __restrict__ hti, const float* __restrict__ HZ0i,
                           const float* __restrict__ HZ1i, const float* __restrict__ XPi,
                           float* __restrict__ Ti)
{
    int w = (blockIdx.x * blockDim.x + threadIdx.x) >> 5;
    int lane = threadIdx.x & 31;
    if (w >= 2 * NNODE) return;
    const bool isU = (w < NNODE);
    const int node = isU ? w : w - NNODE;
    const float* Vr = isU ? Vru : Vri;
    const float* lta = isU ? ltu : lti;
    const float* hta = isU ? htu : hti;
    const float* HZ0 = isU ? HZ0u : HZ0i;
    const float* HZ1 = isU ? HZ1u : HZ1i;
    const float* XP = isU ? XPu : XPi;
    float* T = isU ? Tu : Ti;
    size_t base = (size_t)node * DIM + lane * 4;
    float4 hz0 = *(const float4*)(HZ0 + base);
    float4 hz1 = *(const float4*)(HZ1 + base);
    float4 xp  = *(const float4*)(XP + base);
    float s0 = hz0.x * xp.x + hz0.y * xp.y + hz0.z * xp.z + hz0.w * xp.w;
    float s1 = hz1.x * xp.x + hz1.y * xp.y + hz1.z * xp.z + hz1.w * xp.w;
#pragma unroll
    for (int o = 16; o > 0; o >>= 1) {
        s0 += __shfl_xor_sync(0xffffffffu, s0, o);
        s1 += __shfl_xor_sync(0xffffffffu, s1, o);
    }
    float m = fmaxf(s0, s1);
    float e0 = __expf(s0 - m), e1 = __expf(s1 - m);
    float inv = 1.0f / (e0 + e1);
    float sc0 = e0 * inv, sc1 = e1 * inv;
    float4 ori = *(const float4*)(Vr + base);
    float4 la  = *(const float4*)(lta + base);
    float4 ha  = *(const float4*)(hta + base);
    float4 t;
    t.x = (ori.x + la.x) * sc0 + (ori.x - ha.x) * sc1;
    t.y = (ori.y + la.y) * sc0 + (ori.y - ha.y) * sc1;
    t.z = (ori.z + la.z) * sc0 + (ori.z - ha.z) * sc1;
    t.w = (ori.w + la.w) * sc0 + (ori.w - ha.w) * sc1;
    *(float4*)(T + base) = t;
}

// ------------------------- launch -------------------------
extern "C" void kernel_launch(void* const* d_in, const int* in_sizes, int n_in,
                              void* d_out, int out_size) {
    const float* h_user = (const float*)d_in[0];
    const float* h_item = (const float*)d_in[1];
    const int* buys_src = (const int*)d_in[2];
    const int* buys_dst = (const int*)d_in[3];
    const int* rev_src  = (const int*)d_in[4];
    const int* rev_dst  = (const int*)d_in[5];
    const float* Wk_u = (const float*)d_in[6];  const float* bk_u = (const float*)d_in[7];
    const float* Wk_i = (const float*)d_in[8];  const float* bk_i = (const float*)d_in[9];
    const float* Wq_u = (const float*)d_in[10]; const float* bq_u = (const float*)d_in[11];
    const float* Wq_i = (const float*)d_in[12]; const float* bq_i = (const float*)d_in[13];
    const float* Wv_u = (const float*)d_in[14]; const float* bv_u = (const float*)d_in[15];
    const float* Wv_i = (const float*)d_in[16]; const float* bv_i = (const float*)d_in[17];
    const float* Wa_u = (const float*)d_in[18]; const float* ba_u = (const float*)d_in[19];
    const float* Wa_i = (const float*)d_in[20]; const float* ba_i = (const float*)d_in[21];
    const float* Wf = (const float*)d_in[22];   const float* bf = (const float*)d_in[23];
    const float* Wx = (const float*)d_in[24];   const float* bx = (const float*)d_in[25];
    const float* rel_pri = (const float*)d_in[26];
    const float* rel_att = (const float*)d_in[27];
    const float* rel_msg = (const float*)d_in[28];
    const float* skip = (const float*)d_in[29];
    float* out_u = (float*)d_out;
    float* out_i = (float*)d_out + (size_t)NNODE * DIM;

    float *Ku, *Ki, *Qu, *Qi, *Vru, *Vri, *Vtu, *Vti;
    float *ltu, *htu, *lti, *hti, *HZ0, *HZ1, *XP, *T;
    float *fWku, *fbku, *fWki, *fbki, *fWvu, *fbvu, *fWvi, *fbvi;
    int *counts, *cursor, *offsets, *elist, *bsums;
#define SYM(p, s) cudaGetSymbolAddress((void**)&p, s)
    SYM(Ku, g_Ku); SYM(Ki, g_Ki); SYM(Qu, g_Qu); SYM(Qi, g_Qi);
    SYM(Vru, g_Vru); SYM(Vri, g_Vri); SYM(Vtu, g_Vtu); SYM(Vti, g_Vti);
    SYM(ltu, g_ltu); SYM(htu, g_htu); SYM(lti, g_lti); SYM(hti, g_hti);
    SYM(HZ0, g_HZ0); SYM(HZ1, g_HZ1); SYM(XP, g_XP); SYM(T, g_T);
    SYM(counts, g_counts); SYM(cursor, g_cursor); SYM(offsets, g_offsets); SYM(elist, g_elist);
    SYM(bsums, g_bsums);
    SYM(fWku, g_fWku); SYM(fbku, g_fbku); SYM(fWki, g_fWki); SYM(fbki, g_fbki);
    SYM(fWvu, g_fWvu); SYM(fbvu, g_fbvu); SYM(fWvi, g_fWvi); SYM(fbvi, g_fbvi);
#undef SYM
    // buffer reuse after attention: Ku->HZ0i, Qu->HZ1i, Ki->XPi, Qi->Ti
    float *HZ0i = Ku, *HZ1i = Qu, *XPi = Ki, *Ti = Qi;

    const int gemmGridBF = (NNODE + BM - 1) / BM;
    const int gemmGridFP = (NNODE + 63) / 64;
    const int edgeGrid2 = (2 * NEDGE + 255) / 256;
    const int warpGrid2 = (2 * NNODE * 32 + 255) / 256;
    const int zeroGrid2 = (2 * NNODE + 255) / 256;
    const int scanBlocks2 = (2 * NNODE + 1023) / 1024;

    GemmJob JZ = {nullptr, nullptr, nullptr, nullptr, nullptr, nullptr, nullptr, 0};

    // 1) fused weights (one launch)
    dim3 fuseGrid((DIM * DIM + DIM + 255) / 256, 4);
    fuse_k4<<<fuseGrid, 256>>>(
        Wk_u, bk_u, rel_att, fWku, fbku,
        Wk_i, bk_i, rel_att + NHEAD * 256, fWki, fbki,
        Wv_u, bv_u, rel_msg, fWvu, fbvu,
        Wv_i, bv_i, rel_msg + NHEAD * 256, fWvi, fbvi);

    // 2) CSR build for BOTH relations
    zero_ints<<<zeroGrid2, 256>>>(counts, 2 * NNODE);
    count_edges2<<<edgeGrid2, 256>>>(buys_dst, rev_dst, counts);
    scan_blocks<<<scanBlocks2, 1024>>>(counts, offsets, bsums, 2 * NNODE);
    scan_sums<<<1, 128>>>(bsums, scanBlocks2);
    add_carry<<<scanBlocks2, 1024>>>(offsets, bsums, cursor, 2 * NNODE);
    scatter_edges2<<<edgeGrid2, 256>>>(buys_src, buys_dst, rev_src, rev_dst, offsets, cursor, elist);

    // 3) K/Q projections, exact fp32, one launch (y=4)
    gemm128_fp32_x4<<<dim3(gemmGridFP, 4), 256>>>(
        h_user, fWku, fbku, Ku,
        h_user, Wq_u, bq_u, Qu,
        h_item, fWki, fbki, Ki,
        h_item, Wq_i, bq_i, Qi, NNODE);

    // 4) V projections, bf16x3, one launch (y=4)
    {
        GemmJob a = {h_user, nullptr, Wv_u, bv_u, nullptr, nullptr, Vru, 0};
        GemmJob b = {h_item, nullptr, Wv_i, bv_i, nullptr, nullptr, Vri, 0};
        GemmJob c = {h_user, nullptr, fWvu, fbvu, nullptr, nullptr, Vtu, 0};
        GemmJob d = {h_item, nullptr, fWvi, fbvi, nullptr, nullptr, Vti, 0};
        gemm128_bf16_batch<0,0,4><<<dim3(gemmGridBF, 4), 256>>>(a, b, c, d, JZ, JZ, NNODE);
    }

    // 5) attention, both relations, online softmax (one launch)
    attn_agg2<<<warpGrid2, 256>>>(Qi, Ku, Vtu, Qu, Ki, Vti, offsets, elist, rel_pri,
                                  lti, hti, ltu, htu);

    // 6) update GEMMs, both node types, one launch (y=6) -- item outputs reuse free K/Q buffers
    {
        GemmJob a = {Vru, ltu, Wf, bf, nullptr, nullptr, HZ0, 1};
        GemmJob b = {Vru, htu, Wf, bf, nullptr, nullptr, HZ1, 2};
        GemmJob c = {Vru, nullptr, Wx, bx, nullptr, nullptr, XP, 0};
        GemmJob d = {Vri, lti, Wf, bf, nullptr, nullptr, HZ0i, 1};
        GemmJob e = {Vri, hti, Wf, bf, nullptr, nullptr, HZ1i, 2};
        GemmJob f = {Vri, nullptr, Wx, bx, nullptr, nullptr, XPi, 0};
        gemm128_bf16_batch<1,0,6><<<dim3(gemmGridBF, 6), 256>>>(a, b, c, d, e, f, NNODE);
    }

    // 7) gate + blend, both node types (one launch)
    compute_T2<<<warpGrid2, 256>>>(Vru, ltu, htu, HZ0, HZ1, XP, T,
                                   Vri, lti, hti, HZ0i, HZ1i, XPi, Ti);

    // 8) output GEMMs, both node types (y=2)
    {
        GemmJob a = {T, nullptr, Wa_u, ba_u, h_user, skip + 0, out_u, 0};
        GemmJob b = {Ti, nullptr, Wa_i, ba_i, h_item, skip + 1, out_i, 0};
        gemm128_bf16_batch<0,1,2><<<dim3(gemmGridBF, 2), 256>>>(a, b, JZ, JZ, JZ, JZ, NNODE);
    }
}